// round 14
// baseline (speedup 1.0000x reference)
#include <cuda_runtime.h>

// YOLOv2 loss, B=64, A=5, C=80, G=32, N=50. R13 chassis + TWO-SIDED exact
// area prune (0.6*sa < sb_max AND sa > 0.6*sb_min) + HW tanh sigmoid.
#define NGT 50
#define MAIN_BLOCKS 640          // 64 batches x 10 segs of 512 boxes (2 consecutive boxes/thread)
#define GATH_BLOCKS 400          // 3200 GTs / 8 warps per 256-thread block
#define TOTAL_BLOCKS (MAIN_BLOCKS + GATH_BLOCKS)

__device__ float g_noobj[MAIN_BLOCKS];
__device__ float g_prior[MAIN_BLOCKS];
__device__ float g_coord[GATH_BLOCKS];
__device__ float g_obj[GATH_BLOCKS];
__device__ float g_cls[GATH_BLOCKS];
__device__ unsigned int g_count = 0;

__device__ __forceinline__ float sigm(float x) {
    float t;
    asm("tanh.approx.f32 %0, %1;" : "=f"(t) : "f"(0.5f * x));
    return fmaf(0.5f, t, 0.5f);
}

__global__ void __launch_bounds__(256, 8) fused_kernel(const float* __restrict__ pred,
                                                       const float* __restrict__ gt,
                                                       const float* __restrict__ anc,
                                                       const int* __restrict__ seen,
                                                       float* __restrict__ out)
{
    int tid = threadIdx.x;
    int wid = tid >> 5, lane = tid & 31;

    if (blockIdx.x < MAIN_BLOCKS) {
        // ============== MAIN PATH: noobj + prior over all 327680 boxes ==============
        __shared__ float4 sbox[NGT];       // gt xyxy by GT index
        __shared__ float4 cbox[NGT + 5];   // compacted + padded gt xyxy
        __shared__ float  cssa[NGT + 5];   // compacted + padded 0.375*gt_area
        __shared__ float  swmax[8];        // per-warp max of sb
        __shared__ float  swmin[8];        // per-warp min of sb
        __shared__ unsigned int sbal[2];
        __shared__ unsigned char flag[512];
        __shared__ float  sred[16];

        int b    = blockIdx.x / 10;
        int seg  = blockIdx.x % 10;
        int base = seg * 512;
        int a    = base >> 10;             // uniform anchor for this block
        int cb   = base & 1023;            // 0 or 512
        int c0   = cb + 2 * tid;           // two CONSECUTIVE boxes -> float2 loads
        const float* pp = pred + (((size_t)(b * 425 + a * 85)) << 10);

        float2 dxv = *(const float2*)(pp + c0);
        float2 dyv = *(const float2*)(pp + c0 + 1024);
        float2 twv = *(const float2*)(pp + c0 + 2048);
        float2 thv = *(const float2*)(pp + c0 + 3072);
        float2 tov = *(const float2*)(pp + c0 + 4096);

        flag[tid] = 0; flag[tid + 256] = 0;

        int mybb = -1; float ga_r = 0.0f;
        if (tid < NGT) {
            const float* g = gt + (size_t)(b * NGT + tid) * 7;
            float gdx = g[0], gdy = g[1], gx = g[2], gy = g[3], gw = g[4], gh = g[5];
            ga_r = gw * gh;
            float best = -1.0f; int bp = 0;
            #pragma unroll
            for (int aa = 0; aa < 5; aa++) {
                float aw = __ldg(&anc[2 * aa]), ah = __ldg(&anc[2 * aa + 1]);
                float it = fminf(gw, aw) * fminf(gh, ah);
                float iou = __fdividef(it, ga_r + aw * ah - it);
                if (iou > best) { best = iou; bp = aa; }
            }
            mybb = bp * 1024 + (int)gy * 32 + (int)gx;
            float cx = gdx + gx * (1.0f / 32.0f), cy = gdy + gy * (1.0f / 32.0f);
            sbox[tid] = make_float4(cx - 0.5f * gw, cy - 0.5f * gh, cx + 0.5f * gw, cy + 0.5f * gh);
        }

        // per-box params + block max/min of pred area sb
        float sdx0 = sigm(dxv.x), sdy0 = sigm(dyv.x), so0 = sigm(tov.x);
        float sdx1 = sigm(dxv.y), sdy1 = sigm(dyv.y), so1 = sigm(tov.y);
        float tw0 = twv.x, tw1 = twv.y, th0 = thv.x, th1 = thv.y;
        int x0i = c0 & 31, y0i = (c0 >> 5);
        float cx0 = sdx0 + (float)x0i * (1.0f / 32.0f);
        float cy0 = sdy0 + (float)y0i * (1.0f / 32.0f);
        float cx1 = sdx1 + (float)(x0i + 1) * (1.0f / 32.0f);
        float cy1 = sdy1 + (float)y0i * (1.0f / 32.0f);
        float aw = __ldg(&anc[2 * a]), ah = __ldg(&anc[2 * a + 1]);
        float pw0 = aw * __expf(tw0), ph0 = ah * __expf(th0);
        float pw1 = aw * __expf(tw1), ph1 = ah * __expf(th1);
        float x10 = cx0 - 0.5f*pw0, y10 = cy0 - 0.5f*ph0, x20 = cx0 + 0.5f*pw0, y20 = cy0 + 0.5f*ph0;
        float x11 = cx1 - 0.5f*pw1, y11 = cy1 - 0.5f*ph1, x21 = cx1 + 0.5f*pw1, y21 = cy1 + 0.5f*ph1;
        float sb0 = pw0 * ph0, sb1 = pw1 * ph1;
        float t0_ = 0.375f * sb0, t1_ = 0.375f * sb1;

        float sbM = fmaxf(sb0, sb1), sbm = fminf(sb0, sb1);
        #pragma unroll
        for (int off = 16; off; off >>= 1) {
            sbM = fmaxf(sbM, __shfl_xor_sync(0xffffffffu, sbM, off));
            sbm = fminf(sbm, __shfl_xor_sync(0xffffffffu, sbm, off));
        }
        if (lane == 0) { swmax[wid] = sbM; swmin[wid] = sbm; }
        __syncthreads();   // sbox, swmax/min, zeroed flags visible

        // scatter best-box flags
        if (mybb >= base && mybb < base + 512) flag[mybb - base] = 1;

        // TWO-SIDED exact prune:
        //   trigger needs inter > 0.375(sa+sb); inter <= min(sa,sb)
        //   => sb > 0.6*sa  AND  sa > 0.6*sb   (area band)
        //   block-level: keep GT iff 0.6*sa < max(sb) AND sa > 0.6*min(sb)
        float bmax = fmaxf(fmaxf(fmaxf(swmax[0], swmax[1]), fmaxf(swmax[2], swmax[3])),
                           fmaxf(fmaxf(swmax[4], swmax[5]), fmaxf(swmax[6], swmax[7])));
        float bmin = fminf(fminf(fminf(swmin[0], swmin[1]), fminf(swmin[2], swmin[3])),
                           fminf(fminf(swmin[4], swmin[5]), fminf(swmin[6], swmin[7])));
        bool keep = (tid < NGT) && (0.6f * ga_r < bmax) && (ga_r > 0.6f * bmin);
        if (wid < 2) {
            unsigned int bal = __ballot_sync(0xffffffffu, keep);
            if (lane == 0) sbal[wid] = bal;
        }
        __syncthreads();   // flags + ballots visible
        unsigned int bal0 = sbal[0], bal1 = sbal[1];
        int cnt0 = __popc(bal0);
        int cnt  = cnt0 + __popc(bal1);
        int padded = (cnt + 4) / 5 * 5;
        if (keep) {
            unsigned int mybal = (wid == 0) ? bal0 : bal1;
            int pos = (wid == 0 ? 0 : cnt0) + __popc(mybal & ((1u << lane) - 1u));
            cbox[pos] = sbox[tid];
            cssa[pos] = 0.375f * ga_r;
        }
        // poison-pad to multiple of 5 so the loop stays statically unrolled
        if (tid < padded - cnt) {
            cbox[cnt + tid] = make_float4(1e30f, 1e30f, -1e30f, -1e30f);
            cssa[cnt + tid] = 1e30f;
        }
        __syncthreads();   // compacted list ready

        // consume post-loop state now (flags final)
        bool ib0 = flag[2 * tid] != 0, ib1 = flag[2 * tid + 1] != 0;
        float noc0 = (!ib0) ? so0 * so0 : 0.0f;
        float noc1 = (!ib1) ? so1 * so1 : 0.0f;
        float pr = 0.0f;
        if (!ib0) { float d0 = sdx0 - 0.015625f, d1 = sdy0 - 0.015625f; pr += d0*d0 + d1*d1 + tw0*tw0 + th0*th0; }
        if (!ib1) { float d0 = sdx1 - 0.015625f, d1 = sdy1 - 0.015625f; pr += d0*d0 + d1*d1 + tw1*tw1 + th1*th1; }

        // over-test:  iou > 0.6  <=>  inter - 0.375*sa > 0.375*sb   (division-free)
        float m0 = -1e30f, m1 = -1e30f;
        for (int n = 0; n < padded; n += 5) {
            #pragma unroll
            for (int u = 0; u < 5; u++) {
                float4 gb = cbox[n + u]; float s6 = cssa[n + u];
                // h unclamped: if h<0 then max(w,0)*h <= 0 and -s6 < 0 < t_, never triggers.
                float w0 = fminf(x20, gb.z) - fmaxf(x10, gb.x);
                float h0 = fminf(y20, gb.w) - fmaxf(y10, gb.y);
                m0 = fmaxf(m0, fmaf(fmaxf(w0, 0.0f), h0, -s6));
                float w1 = fminf(x21, gb.z) - fmaxf(x11, gb.x);
                float h1 = fminf(y21, gb.w) - fmaxf(y11, gb.y);
                m1 = fmaxf(m1, fmaf(fmaxf(w1, 0.0f), h1, -s6));
            }
        }
        float no = 0.0f;
        if (!(m0 > t0_)) no += noc0;
        if (!(m1 > t1_)) no += noc1;

        #pragma unroll
        for (int off = 16; off; off >>= 1) {
            no += __shfl_down_sync(0xffffffffu, no, off);
            pr += __shfl_down_sync(0xffffffffu, pr, off);
        }
        if (lane == 0) { sred[wid] = no; sred[8 + wid] = pr; }
        __syncthreads();
        if (tid == 0) {
            float s = 0.0f;
            #pragma unroll
            for (int i = 0; i < 8; i++) s += sred[i];
            g_noobj[blockIdx.x] = s;
        }
        if (tid == 32) {
            float s = 0.0f;
            #pragma unroll
            for (int i = 0; i < 8; i++) s += sred[8 + i];
            g_prior[blockIdx.x] = s;
        }
    } else {
        // ============== GATHER PATH: coord + obj + cls at 3200 best boxes ==============
        __shared__ float sc[8], so_[8], sl[8];
        int gb_ = blockIdx.x - MAIN_BLOCKS;
        int gtid = gb_ * 8 + wid;
        int b = gtid / NGT;

        const float* g = gt + (size_t)gtid * 7;   // broadcast loads across warp
        float gdx = g[0], gdy = g[1], gx = g[2], gy = g[3], gw = g[4], gh = g[5];
        int k = (int)g[6];
        float ga = gw * gh;
        float best = -1.0f; int bp = 0;
        #pragma unroll
        for (int a = 0; a < 5; a++) {
            float aw = __ldg(&anc[2 * a]), ah = __ldg(&anc[2 * a + 1]);
            float it = fminf(gw, aw) * fminf(gh, ah);
            float iou = __fdividef(it, ga + aw * ah - it);
            if (iou > best) { best = iou; bp = a; }
        }
        int cell = (int)gy * 32 + (int)gx;
        const float* pp = pred + (((size_t)(b * 425 + bp * 85)) << 10) + cell;

        // one-pass softmax-MSE: sum_c (p_c - 1[c=k])^2 = Q/S^2 - 2 e_k/S + 1
        float S = 0.0f, Q = 0.0f, ek = 0.0f;
        {
            float e0 = __expf(pp[(size_t)(5 + lane) << 10]);  S += e0; Q += e0 * e0; if (lane == k) ek = e0;
            float e1 = __expf(pp[(size_t)(37 + lane) << 10]); S += e1; Q += e1 * e1; if (lane + 32 == k) ek = e1;
            if (lane < 16) {
                float e2 = __expf(pp[(size_t)(69 + lane) << 10]); S += e2; Q += e2 * e2; if (lane + 64 == k) ek = e2;
            }
        }
        #pragma unroll
        for (int off = 16; off; off >>= 1) {
            S  += __shfl_xor_sync(0xffffffffu, S,  off);
            Q  += __shfl_xor_sync(0xffffffffu, Q,  off);
            ek += __shfl_xor_sync(0xffffffffu, ek, off);
        }

        float sdx = sigm(pp[0]), sdy = sigm(pp[1024]);
        float tw = pp[2048], th = pp[3072], sobj = sigm(pp[4096]);
        float aw = __ldg(&anc[2 * bp]), ah = __ldg(&anc[2 * bp + 1]);
        float d0 = sdx - gdx, d1 = sdy - gdy;
        float d2 = tw - (__logf(gw) - __logf(aw));
        float d3 = th - (__logf(gh) - __logf(ah));
        float coord = d0*d0 + d1*d1 + d2*d2 + d3*d3;

        float cx = sdx + (float)(cell & 31) * (1.0f / 32.0f);
        float cy = sdy + (float)(cell >> 5) * (1.0f / 32.0f);
        float pw = aw * __expf(tw), ph = ah * __expf(th);
        float gx1 = (gdx + gx * (1.0f / 32.0f)) - 0.5f * gw;
        float gy1 = (gdy + gy * (1.0f / 32.0f)) - 0.5f * gh;
        float w = fminf(cx + 0.5f * pw, gx1 + gw) - fmaxf(cx - 0.5f * pw, gx1);
        float h = fminf(cy + 0.5f * ph, gy1 + gh) - fmaxf(cy - 0.5f * ph, gy1);
        float inter = fmaxf(w, 0.0f) * fmaxf(h, 0.0f);
        float iou_t = __fdividef(inter, ga + pw * ph - inter);
        float di = sobj - iou_t;
        float obj = di * di;
        float invS = __fdividef(1.0f, S);
        float cls = fmaf(Q * invS, invS, fmaf(-2.0f * ek, invS, 1.0f));

        if (lane == 0) { sc[wid] = coord; so_[wid] = obj; sl[wid] = cls; }
        __syncthreads();
        if (tid == 0) {
            float tc = 0.f, to_ = 0.f, tl = 0.f;
            #pragma unroll
            for (int i = 0; i < 8; i++) { tc += sc[i]; to_ += so_[i]; tl += sl[i]; }
            g_coord[gb_] = tc;
            g_obj[gb_]   = to_;
            g_cls[gb_]   = tl;
        }
    }

    // ---------------- last-block deterministic final combine ----------------
    __shared__ bool is_last;
    __shared__ float sm[40];
    __syncthreads();
    if (threadIdx.x == 0) {
        __threadfence();
        unsigned int c = atomicAdd(&g_count, 1u);
        is_last = (c == TOTAL_BLOCKS - 1);
    }
    __syncthreads();
    if (!is_last) return;
    __threadfence();  // make all blocks' partials visible

    float a0 = 0.f, a1 = 0.f, a2 = 0.f, a3 = 0.f, a4 = 0.f;
    for (int i = tid; i < MAIN_BLOCKS; i += 256) { a0 += g_noobj[i]; a1 += g_prior[i]; }
    for (int i = tid; i < GATH_BLOCKS; i += 256) { a2 += g_coord[i]; a3 += g_obj[i]; a4 += g_cls[i]; }
    #pragma unroll
    for (int off = 16; off; off >>= 1) {
        a0 += __shfl_down_sync(0xffffffffu, a0, off);
        a1 += __shfl_down_sync(0xffffffffu, a1, off);
        a2 += __shfl_down_sync(0xffffffffu, a2, off);
        a3 += __shfl_down_sync(0xffffffffu, a3, off);
        a4 += __shfl_down_sync(0xffffffffu, a4, off);
    }
    if (lane == 0) {
        sm[wid] = a0; sm[8 + wid] = a1; sm[16 + wid] = a2; sm[24 + wid] = a3; sm[32 + wid] = a4;
    }
    __syncthreads();
    if (tid == 0) {
        float t0 = 0.f, t1 = 0.f, t2 = 0.f, t3 = 0.f, t4 = 0.f;
        #pragma unroll
        for (int i = 0; i < 8; i++) {
            t0 += sm[i]; t1 += sm[8 + i]; t2 += sm[16 + i]; t3 += sm[24 + i]; t4 += sm[32 + i];
        }
        float lp = (seen[0] < 12800) ? 0.01f : 0.0f;
        out[0] = t4 + t0 + 5.0f * t3 + t2 + lp * t1;
        g_count = 0;   // reset for next graph replay
    }
}

extern "C" void kernel_launch(void* const* d_in, const int* in_sizes, int n_in,
                              void* d_out, int out_size) {
    const float* pred = (const float*)d_in[0];
    const float* gt   = (const float*)d_in[1];
    const float* anc  = (const float*)d_in[2];
    const int*   seen = (const int*)d_in[3];
    (void)in_sizes; (void)n_in; (void)out_size;

    fused_kernel<<<TOTAL_BLOCKS, 256>>>(pred, gt, anc, seen, (float*)d_out);
}

// round 15
// speedup vs baseline: 1.0151x; 1.0151x over previous
#include <cuda_runtime.h>

// YOLOv2 loss, B=64, A=5, C=80, G=32, N=50. Single kernel; GATHER BLOCKS FIRST
// (latency-bound scattered loads overlap under compute-heavy main blocks),
// one-sided exact GT-area prune, padded static-unroll loop, float2 loads.
#define NGT 50
#define MAIN_BLOCKS 640          // 64 batches x 10 segs of 512 boxes (2 consecutive boxes/thread)
#define GATH_BLOCKS 400          // 3200 GTs / 8 warps per 256-thread block
#define TOTAL_BLOCKS (MAIN_BLOCKS + GATH_BLOCKS)

__device__ float g_noobj[MAIN_BLOCKS];
__device__ float g_prior[MAIN_BLOCKS];
__device__ float g_coord[GATH_BLOCKS];
__device__ float g_obj[GATH_BLOCKS];
__device__ float g_cls[GATH_BLOCKS];
__device__ unsigned int g_count = 0;

__device__ __forceinline__ float sigm(float x) {
    float t;
    asm("tanh.approx.f32 %0, %1;" : "=f"(t) : "f"(0.5f * x));
    return fmaf(0.5f, t, 0.5f);
}

__global__ void __launch_bounds__(256, 8) fused_kernel(const float* __restrict__ pred,
                                                       const float* __restrict__ gt,
                                                       const float* __restrict__ anc,
                                                       const int* __restrict__ seen,
                                                       float* __restrict__ out)
{
    int tid = threadIdx.x;
    int wid = tid >> 5, lane = tid & 31;

    if (blockIdx.x >= GATH_BLOCKS) {
        // ============== MAIN PATH: noobj + prior over all 327680 boxes ==============
        __shared__ float4 sbox[NGT];       // gt xyxy by GT index
        __shared__ float4 cbox[NGT + 5];   // compacted + padded gt xyxy
        __shared__ float  cssa[NGT + 5];   // compacted + padded 0.375*gt_area
        __shared__ float  swmax[8];        // per-warp max of sb
        __shared__ unsigned int sbal[2];
        __shared__ unsigned char flag[512];
        __shared__ float  sred[16];

        int mb   = blockIdx.x - GATH_BLOCKS;
        int b    = mb / 10;
        int seg  = mb % 10;
        int base = seg * 512;
        int a    = base >> 10;             // uniform anchor for this block
        int cb   = base & 1023;            // 0 or 512
        int c0   = cb + 2 * tid;           // two CONSECUTIVE boxes -> float2 loads
        const float* pp = pred + (((size_t)(b * 425 + a * 85)) << 10);

        float2 dxv = *(const float2*)(pp + c0);
        float2 dyv = *(const float2*)(pp + c0 + 1024);
        float2 twv = *(const float2*)(pp + c0 + 2048);
        float2 thv = *(const float2*)(pp + c0 + 3072);
        float2 tov = *(const float2*)(pp + c0 + 4096);

        flag[tid] = 0; flag[tid + 256] = 0;

        int mybb = -1; float ga_r = 0.0f;
        if (tid < NGT) {
            const float* g = gt + (size_t)(b * NGT + tid) * 7;
            float gdx = g[0], gdy = g[1], gx = g[2], gy = g[3], gw = g[4], gh = g[5];
            ga_r = gw * gh;
            float best = -1.0f; int bp = 0;
            #pragma unroll
            for (int aa = 0; aa < 5; aa++) {
                float aw = __ldg(&anc[2 * aa]), ah = __ldg(&anc[2 * aa + 1]);
                float it = fminf(gw, aw) * fminf(gh, ah);
                float iou = __fdividef(it, ga_r + aw * ah - it);
                if (iou > best) { best = iou; bp = aa; }
            }
            mybb = bp * 1024 + (int)gy * 32 + (int)gx;
            float cx = gdx + gx * (1.0f / 32.0f), cy = gdy + gy * (1.0f / 32.0f);
            sbox[tid] = make_float4(cx - 0.5f * gw, cy - 0.5f * gh, cx + 0.5f * gw, cy + 0.5f * gh);
        }

        // per-box params + block max of pred area sb
        float sdx0 = sigm(dxv.x), sdy0 = sigm(dyv.x), so0 = sigm(tov.x);
        float sdx1 = sigm(dxv.y), sdy1 = sigm(dyv.y), so1 = sigm(tov.y);
        float tw0 = twv.x, tw1 = twv.y, th0 = thv.x, th1 = thv.y;
        int x0i = c0 & 31, y0i = (c0 >> 5);
        float cx0 = sdx0 + (float)x0i * (1.0f / 32.0f);
        float cy0 = sdy0 + (float)y0i * (1.0f / 32.0f);
        float cx1 = sdx1 + (float)(x0i + 1) * (1.0f / 32.0f);
        float cy1 = sdy1 + (float)y0i * (1.0f / 32.0f);
        float aw = __ldg(&anc[2 * a]), ah = __ldg(&anc[2 * a + 1]);
        float pw0 = aw * __expf(tw0), ph0 = ah * __expf(th0);
        float pw1 = aw * __expf(tw1), ph1 = ah * __expf(th1);
        float x10 = cx0 - 0.5f*pw0, y10 = cy0 - 0.5f*ph0, x20 = cx0 + 0.5f*pw0, y20 = cy0 + 0.5f*ph0;
        float x11 = cx1 - 0.5f*pw1, y11 = cy1 - 0.5f*ph1, x21 = cx1 + 0.5f*pw1, y21 = cy1 + 0.5f*ph1;
        float sb0 = pw0 * ph0, sb1 = pw1 * ph1;
        float t0_ = 0.375f * sb0, t1_ = 0.375f * sb1;

        float sbm = fmaxf(sb0, sb1);
        #pragma unroll
        for (int off = 16; off; off >>= 1)
            sbm = fmaxf(sbm, __shfl_xor_sync(0xffffffffu, sbm, off));
        if (lane == 0) swmax[wid] = sbm;
        __syncthreads();   // sbox, swmax, zeroed flags visible

        // scatter best-box flags
        if (mybb >= base && mybb < base + 512) flag[mybb - base] = 1;

        // exact prune: GT n can trigger only if 0.6*ga_n < max_block(sb)  (inter <= sb)
        float bmax = fmaxf(fmaxf(fmaxf(swmax[0], swmax[1]), fmaxf(swmax[2], swmax[3])),
                           fmaxf(fmaxf(swmax[4], swmax[5]), fmaxf(swmax[6], swmax[7])));
        bool keep = (tid < NGT) && (0.6f * ga_r < bmax);
        if (wid < 2) {
            unsigned int bal = __ballot_sync(0xffffffffu, keep);
            if (lane == 0) sbal[wid] = bal;
        }
        __syncthreads();   // flags + ballots visible
        unsigned int bal0 = sbal[0], bal1 = sbal[1];
        int cnt0 = __popc(bal0);
        int cnt  = cnt0 + __popc(bal1);
        int padded = (cnt + 4) / 5 * 5;
        if (keep) {
            unsigned int mybal = (wid == 0) ? bal0 : bal1;
            int pos = (wid == 0 ? 0 : cnt0) + __popc(mybal & ((1u << lane) - 1u));
            cbox[pos] = sbox[tid];
            cssa[pos] = 0.375f * ga_r;
        }
        // poison-pad to multiple of 5 so the loop stays statically unrolled
        if (tid < padded - cnt) {
            cbox[cnt + tid] = make_float4(1e30f, 1e30f, -1e30f, -1e30f);
            cssa[cnt + tid] = 1e30f;
        }
        __syncthreads();   // compacted list ready

        // consume post-loop state now (flags final)
        bool ib0 = flag[2 * tid] != 0, ib1 = flag[2 * tid + 1] != 0;
        float noc0 = (!ib0) ? so0 * so0 : 0.0f;
        float noc1 = (!ib1) ? so1 * so1 : 0.0f;
        float pr = 0.0f;
        if (!ib0) { float d0 = sdx0 - 0.015625f, d1 = sdy0 - 0.015625f; pr += d0*d0 + d1*d1 + tw0*tw0 + th0*th0; }
        if (!ib1) { float d0 = sdx1 - 0.015625f, d1 = sdy1 - 0.015625f; pr += d0*d0 + d1*d1 + tw1*tw1 + th1*th1; }

        // over-test:  iou > 0.6  <=>  inter - 0.375*sa > 0.375*sb   (division-free)
        float m0 = -1e30f, m1 = -1e30f;
        for (int n = 0; n < padded; n += 5) {
            #pragma unroll
            for (int u = 0; u < 5; u++) {
                float4 gb = cbox[n + u]; float s6 = cssa[n + u];
                // h unclamped: if h<0 then max(w,0)*h <= 0 and -s6 < 0 < t_, never triggers.
                float w0 = fminf(x20, gb.z) - fmaxf(x10, gb.x);
                float h0 = fminf(y20, gb.w) - fmaxf(y10, gb.y);
                m0 = fmaxf(m0, fmaf(fmaxf(w0, 0.0f), h0, -s6));
                float w1 = fminf(x21, gb.z) - fmaxf(x11, gb.x);
                float h1 = fminf(y21, gb.w) - fmaxf(y11, gb.y);
                m1 = fmaxf(m1, fmaf(fmaxf(w1, 0.0f), h1, -s6));
            }
        }
        float no = 0.0f;
        if (!(m0 > t0_)) no += noc0;
        if (!(m1 > t1_)) no += noc1;

        #pragma unroll
        for (int off = 16; off; off >>= 1) {
            no += __shfl_down_sync(0xffffffffu, no, off);
            pr += __shfl_down_sync(0xffffffffu, pr, off);
        }
        if (lane == 0) { sred[wid] = no; sred[8 + wid] = pr; }
        __syncthreads();
        if (tid == 0) {
            float s = 0.0f;
            #pragma unroll
            for (int i = 0; i < 8; i++) s += sred[i];
            g_noobj[mb] = s;
        }
        if (tid == 32) {
            float s = 0.0f;
            #pragma unroll
            for (int i = 0; i < 8; i++) s += sred[8 + i];
            g_prior[mb] = s;
        }
    } else {
        // ============== GATHER PATH (FIRST in grid): coord + obj + cls ==============
        __shared__ float sc[8], so_[8], sl[8];
        int gb_ = blockIdx.x;
        int gtid = gb_ * 8 + wid;
        int b = gtid / NGT;

        const float* g = gt + (size_t)gtid * 7;   // broadcast loads across warp
        float gdx = g[0], gdy = g[1], gx = g[2], gy = g[3], gw = g[4], gh = g[5];
        int k = (int)g[6];
        float ga = gw * gh;
        float best = -1.0f; int bp = 0;
        #pragma unroll
        for (int a = 0; a < 5; a++) {
            float aw = __ldg(&anc[2 * a]), ah = __ldg(&anc[2 * a + 1]);
            float it = fminf(gw, aw) * fminf(gh, ah);
            float iou = __fdividef(it, ga + aw * ah - it);
            if (iou > best) { best = iou; bp = a; }
        }
        int cell = (int)gy * 32 + (int)gx;
        const float* pp = pred + (((size_t)(b * 425 + bp * 85)) << 10) + cell;

        // one-pass softmax-MSE: sum_c (p_c - 1[c=k])^2 = Q/S^2 - 2 e_k/S + 1
        float S = 0.0f, Q = 0.0f, ek = 0.0f;
        {
            float e0 = __expf(pp[(size_t)(5 + lane) << 10]);  S += e0; Q += e0 * e0; if (lane == k) ek = e0;
            float e1 = __expf(pp[(size_t)(37 + lane) << 10]); S += e1; Q += e1 * e1; if (lane + 32 == k) ek = e1;
            if (lane < 16) {
                float e2 = __expf(pp[(size_t)(69 + lane) << 10]); S += e2; Q += e2 * e2; if (lane + 64 == k) ek = e2;
            }
        }
        #pragma unroll
        for (int off = 16; off; off >>= 1) {
            S  += __shfl_xor_sync(0xffffffffu, S,  off);
            Q  += __shfl_xor_sync(0xffffffffu, Q,  off);
            ek += __shfl_xor_sync(0xffffffffu, ek, off);
        }

        float sdx = sigm(pp[0]), sdy = sigm(pp[1024]);
        float tw = pp[2048], th = pp[3072], sobj = sigm(pp[4096]);
        float aw = __ldg(&anc[2 * bp]), ah = __ldg(&anc[2 * bp + 1]);
        float d0 = sdx - gdx, d1 = sdy - gdy;
        float d2 = tw - (__logf(gw) - __logf(aw));
        float d3 = th - (__logf(gh) - __logf(ah));
        float coord = d0*d0 + d1*d1 + d2*d2 + d3*d3;

        float cx = sdx + (float)(cell & 31) * (1.0f / 32.0f);
        float cy = sdy + (float)(cell >> 5) * (1.0f / 32.0f);
        float pw = aw * __expf(tw), ph = ah * __expf(th);
        float gx1 = (gdx + gx * (1.0f / 32.0f)) - 0.5f * gw;
        float gy1 = (gdy + gy * (1.0f / 32.0f)) - 0.5f * gh;
        float w = fminf(cx + 0.5f * pw, gx1 + gw) - fmaxf(cx - 0.5f * pw, gx1);
        float h = fminf(cy + 0.5f * ph, gy1 + gh) - fmaxf(cy - 0.5f * ph, gy1);
        float inter = fmaxf(w, 0.0f) * fmaxf(h, 0.0f);
        float iou_t = __fdividef(inter, ga + pw * ph - inter);
        float di = sobj - iou_t;
        float obj = di * di;
        float invS = __fdividef(1.0f, S);
        float cls = fmaf(Q * invS, invS, fmaf(-2.0f * ek, invS, 1.0f));

        if (lane == 0) { sc[wid] = coord; so_[wid] = obj; sl[wid] = cls; }
        __syncthreads();
        if (tid == 0) {
            float tc = 0.f, to_ = 0.f, tl = 0.f;
            #pragma unroll
            for (int i = 0; i < 8; i++) { tc += sc[i]; to_ += so_[i]; tl += sl[i]; }
            g_coord[gb_] = tc;
            g_obj[gb_]   = to_;
            g_cls[gb_]   = tl;
        }
    }

    // ---------------- last-block deterministic final combine ----------------
    __shared__ bool is_last;
    __shared__ float sm[40];
    __syncthreads();
    if (threadIdx.x == 0) {
        __threadfence();
        unsigned int c = atomicAdd(&g_count, 1u);
        is_last = (c == TOTAL_BLOCKS - 1);
    }
    __syncthreads();
    if (!is_last) return;
    __threadfence();  // make all blocks' partials visible

    float a0 = 0.f, a1 = 0.f, a2 = 0.f, a3 = 0.f, a4 = 0.f;
    for (int i = tid; i < MAIN_BLOCKS; i += 256) { a0 += g_noobj[i]; a1 += g_prior[i]; }
    for (int i = tid; i < GATH_BLOCKS; i += 256) { a2 += g_coord[i]; a3 += g_obj[i]; a4 += g_cls[i]; }
    #pragma unroll
    for (int off = 16; off; off >>= 1) {
        a0 += __shfl_down_sync(0xffffffffu, a0, off);
        a1 += __shfl_down_sync(0xffffffffu, a1, off);
        a2 += __shfl_down_sync(0xffffffffu, a2, off);
        a3 += __shfl_down_sync(0xffffffffu, a3, off);
        a4 += __shfl_down_sync(0xffffffffu, a4, off);
    }
    if (lane == 0) {
        sm[wid] = a0; sm[8 + wid] = a1; sm[16 + wid] = a2; sm[24 + wid] = a3; sm[32 + wid] = a4;
    }
    __syncthreads();
    if (tid == 0) {
        float t0 = 0.f, t1 = 0.f, t2 = 0.f, t3 = 0.f, t4 = 0.f;
        #pragma unroll
        for (int i = 0; i < 8; i++) {
            t0 += sm[i]; t1 += sm[8 + i]; t2 += sm[16 + i]; t3 += sm[24 + i]; t4 += sm[32 + i];
        }
        float lp = (seen[0] < 12800) ? 0.01f : 0.0f;
        out[0] = t4 + t0 + 5.0f * t3 + t2 + lp * t1;
        g_count = 0;   // reset for next graph replay
    }
}

extern "C" void kernel_launch(void* const* d_in, const int* in_sizes, int n_in,
                              void* d_out, int out_size) {
    const float* pred = (const float*)d_in[0];
    const float* gt   = (const float*)d_in[1];
    const float* anc  = (const float*)d_in[2];
    const int*   seen = (const int*)d_in[3];
    (void)in_sizes; (void)n_in; (void)out_size;

    fused_kernel<<<TOTAL_BLOCKS, 256>>>(pred, gt, anc, seen, (float*)d_out);
}

// round 16
// speedup vs baseline: 1.0173x; 1.0022x over previous
#include <cuda_runtime.h>

// YOLOv2 loss, B=64, A=5, C=80, G=32, N=50. ONE block type: each of 640 blocks
// does 512 main boxes (2/thread, float2 loads, exact GT-area prune) AND 5
// gather GTs (warps 0-4), with gather loads issued early to overlap latency.
#define NGT 50
#define NBLOCKS 640              // 64 batches x 10 segs; 5 gather GTs per block
#define NGPB 5                   // gather GTs per block

__device__ float g_noobj[NBLOCKS];
__device__ float g_prior[NBLOCKS];
__device__ float g_coord[NBLOCKS];
__device__ float g_obj[NBLOCKS];
__device__ float g_cls[NBLOCKS];
__device__ unsigned int g_count = 0;

__device__ __forceinline__ float sigm(float x) {
    float t;
    asm("tanh.approx.f32 %0, %1;" : "=f"(t) : "f"(0.5f * x));
    return fmaf(0.5f, t, 0.5f);
}

__global__ void __launch_bounds__(256, 6) fused_kernel(const float* __restrict__ pred,
                                                       const float* __restrict__ gt,
                                                       const float* __restrict__ anc,
                                                       const int* __restrict__ seen,
                                                       float* __restrict__ out)
{
    int tid = threadIdx.x;
    int wid = tid >> 5, lane = tid & 31;

    __shared__ float4 sbox[NGT];       // gt xyxy by GT index
    __shared__ float4 cbox[NGT + 5];   // compacted + padded gt xyxy
    __shared__ float  cssa[NGT + 5];   // compacted + padded 0.375*gt_area
    __shared__ float  swmax[8];        // per-warp max of sb
    __shared__ unsigned int sbal[2];
    __shared__ unsigned char flag[512];
    __shared__ float  sred[16];
    __shared__ float  gc[NGPB], go[NGPB], gl[NGPB];  // gather results per warp

    int b    = blockIdx.x / 10;
    int seg  = blockIdx.x % 10;
    int base = seg * 512;
    int a    = base >> 10;             // uniform anchor for this block
    int cb   = base & 1023;            // 0 or 512
    int c0   = cb + 2 * tid;           // two CONSECUTIVE boxes -> float2 loads
    const float* pp = pred + (((size_t)(b * 425 + a * 85)) << 10);

    // main-path loads issued first (they gate the IoU loop)
    float2 dxv = *(const float2*)(pp + c0);
    float2 dyv = *(const float2*)(pp + c0 + 1024);
    float2 twv = *(const float2*)(pp + c0 + 2048);
    float2 thv = *(const float2*)(pp + c0 + 3072);
    float2 tov = *(const float2*)(pp + c0 + 4096);

    flag[tid] = 0; flag[tid + 256] = 0;

    int mybb = -1; float ga_r = 0.0f;
    if (tid < NGT) {
        const float* g = gt + (size_t)(b * NGT + tid) * 7;
        float gdx = g[0], gdy = g[1], gx = g[2], gy = g[3], gw = g[4], gh = g[5];
        ga_r = gw * gh;
        float best = -1.0f; int bp = 0;
        #pragma unroll
        for (int aa = 0; aa < 5; aa++) {
            float aw = __ldg(&anc[2 * aa]), ah = __ldg(&anc[2 * aa + 1]);
            float it = fminf(gw, aw) * fminf(gh, ah);
            float iou = __fdividef(it, ga_r + aw * ah - it);
            if (iou > best) { best = iou; bp = aa; }
        }
        mybb = bp * 1024 + (int)gy * 32 + (int)gx;
        float cx = gdx + gx * (1.0f / 32.0f), cy = gdy + gy * (1.0f / 32.0f);
        sbox[tid] = make_float4(cx - 0.5f * gw, cy - 0.5f * gh, cx + 0.5f * gw, cy + 0.5f * gh);
    }

    // ===== GATHER SECTION (warps 0-4): coord + obj + cls for 5 GTs =====
    // Issued early so the ~90 scattered loads overlap the main compute below.
    if (wid < NGPB) {
        int gtid = b * NGT + seg * NGPB + wid;
        const float* g = gt + (size_t)gtid * 7;      // broadcast loads
        float gdx = g[0], gdy = g[1], gx = g[2], gy = g[3], gw = g[4], gh = g[5];
        int k = (int)g[6];
        float ga = gw * gh;
        float best = -1.0f; int bp = 0;
        #pragma unroll
        for (int aa = 0; aa < 5; aa++) {
            float aw = __ldg(&anc[2 * aa]), ah = __ldg(&anc[2 * aa + 1]);
            float it = fminf(gw, aw) * fminf(gh, ah);
            float iou = __fdividef(it, ga + aw * ah - it);
            if (iou > best) { best = iou; bp = aa; }
        }
        int cell = (int)gy * 32 + (int)gx;
        const float* gp = pred + (((size_t)(b * 425 + bp * 85)) << 10) + cell;

        float S = 0.0f, Q = 0.0f, ek = 0.0f;
        {
            float e0 = __expf(gp[(size_t)(5 + lane) << 10]);  S += e0; Q += e0 * e0; if (lane == k) ek = e0;
            float e1 = __expf(gp[(size_t)(37 + lane) << 10]); S += e1; Q += e1 * e1; if (lane + 32 == k) ek = e1;
            if (lane < 16) {
                float e2 = __expf(gp[(size_t)(69 + lane) << 10]); S += e2; Q += e2 * e2; if (lane + 64 == k) ek = e2;
            }
        }
        #pragma unroll
        for (int off = 16; off; off >>= 1) {
            S  += __shfl_xor_sync(0xffffffffu, S,  off);
            Q  += __shfl_xor_sync(0xffffffffu, Q,  off);
            ek += __shfl_xor_sync(0xffffffffu, ek, off);
        }

        float sdx = sigm(gp[0]), sdy = sigm(gp[1024]);
        float tw = gp[2048], th = gp[3072], sobj = sigm(gp[4096]);
        float aw = __ldg(&anc[2 * bp]), ah = __ldg(&anc[2 * bp + 1]);
        float d0 = sdx - gdx, d1 = sdy - gdy;
        float d2 = tw - (__logf(gw) - __logf(aw));
        float d3 = th - (__logf(gh) - __logf(ah));

        float cxg = sdx + (float)(cell & 31) * (1.0f / 32.0f);
        float cyg = sdy + (float)(cell >> 5) * (1.0f / 32.0f);
        float pw = aw * __expf(tw), ph = ah * __expf(th);
        float gxx = (gdx + gx * (1.0f / 32.0f)) - 0.5f * gw;
        float gyy = (gdy + gy * (1.0f / 32.0f)) - 0.5f * gh;
        float w = fminf(cxg + 0.5f * pw, gxx + gw) - fmaxf(cxg - 0.5f * pw, gxx);
        float h = fminf(cyg + 0.5f * ph, gyy + gh) - fmaxf(cyg - 0.5f * ph, gyy);
        float inter = fmaxf(w, 0.0f) * fmaxf(h, 0.0f);
        float iou_t = __fdividef(inter, ga + pw * ph - inter);
        float di = sobj - iou_t;
        float invS = __fdividef(1.0f, S);
        if (lane == 0) {
            gc[wid] = d0*d0 + d1*d1 + d2*d2 + d3*d3;
            go[wid] = di * di;
            gl[wid] = fmaf(Q * invS, invS, fmaf(-2.0f * ek, invS, 1.0f));
        }
    }

    // ===== MAIN SECTION =====
    float sdx0 = sigm(dxv.x), sdy0 = sigm(dyv.x), so0 = sigm(tov.x);
    float sdx1 = sigm(dxv.y), sdy1 = sigm(dyv.y), so1 = sigm(tov.y);
    float tw0 = twv.x, tw1 = twv.y, th0 = thv.x, th1 = thv.y;
    int x0i = c0 & 31, y0i = (c0 >> 5);
    float cx0 = sdx0 + (float)x0i * (1.0f / 32.0f);
    float cy0 = sdy0 + (float)y0i * (1.0f / 32.0f);
    float cx1 = sdx1 + (float)(x0i + 1) * (1.0f / 32.0f);
    float cy1 = sdy1 + (float)y0i * (1.0f / 32.0f);
    float aw = __ldg(&anc[2 * a]), ah = __ldg(&anc[2 * a + 1]);
    float pw0 = aw * __expf(tw0), ph0 = ah * __expf(th0);
    float pw1 = aw * __expf(tw1), ph1 = ah * __expf(th1);
    float x10 = cx0 - 0.5f*pw0, y10 = cy0 - 0.5f*ph0, x20 = cx0 + 0.5f*pw0, y20 = cy0 + 0.5f*ph0;
    float x11 = cx1 - 0.5f*pw1, y11 = cy1 - 0.5f*ph1, x21 = cx1 + 0.5f*pw1, y21 = cy1 + 0.5f*ph1;
    float sb0 = pw0 * ph0, sb1 = pw1 * ph1;
    float t0_ = 0.375f * sb0, t1_ = 0.375f * sb1;

    float sbm = fmaxf(sb0, sb1);
    #pragma unroll
    for (int off = 16; off; off >>= 1)
        sbm = fmaxf(sbm, __shfl_xor_sync(0xffffffffu, sbm, off));
    if (lane == 0) swmax[wid] = sbm;
    __syncthreads();   // sbox, swmax, gc/go/gl, zeroed flags visible

    if (mybb >= base && mybb < base + 512) flag[mybb - base] = 1;

    // exact prune: GT n can trigger only if 0.6*ga_n < max_block(sb)  (inter <= sb)
    float bmax = fmaxf(fmaxf(fmaxf(swmax[0], swmax[1]), fmaxf(swmax[2], swmax[3])),
                       fmaxf(fmaxf(swmax[4], swmax[5]), fmaxf(swmax[6], swmax[7])));
    bool keep = (tid < NGT) && (0.6f * ga_r < bmax);
    if (wid < 2) {
        unsigned int bal = __ballot_sync(0xffffffffu, keep);
        if (lane == 0) sbal[wid] = bal;
    }
    __syncthreads();   // flags + ballots visible
    unsigned int bal0 = sbal[0], bal1 = sbal[1];
    int cnt0 = __popc(bal0);
    int cnt  = cnt0 + __popc(bal1);
    int padded = (cnt + 4) / 5 * 5;
    if (keep) {
        unsigned int mybal = (wid == 0) ? bal0 : bal1;
        int pos = (wid == 0 ? 0 : cnt0) + __popc(mybal & ((1u << lane) - 1u));
        cbox[pos] = sbox[tid];
        cssa[pos] = 0.375f * ga_r;
    }
    if (tid < padded - cnt) {
        cbox[cnt + tid] = make_float4(1e30f, 1e30f, -1e30f, -1e30f);
        cssa[cnt + tid] = 1e30f;
    }
    __syncthreads();   // compacted list ready

    bool ib0 = flag[2 * tid] != 0, ib1 = flag[2 * tid + 1] != 0;
    float noc0 = (!ib0) ? so0 * so0 : 0.0f;
    float noc1 = (!ib1) ? so1 * so1 : 0.0f;
    float pr = 0.0f;
    if (!ib0) { float d0 = sdx0 - 0.015625f, d1 = sdy0 - 0.015625f; pr += d0*d0 + d1*d1 + tw0*tw0 + th0*th0; }
    if (!ib1) { float d0 = sdx1 - 0.015625f, d1 = sdy1 - 0.015625f; pr += d0*d0 + d1*d1 + tw1*tw1 + th1*th1; }

    // over-test:  iou > 0.6  <=>  inter - 0.375*sa > 0.375*sb   (division-free)
    float m0 = -1e30f, m1 = -1e30f;
    for (int n = 0; n < padded; n += 5) {
        #pragma unroll
        for (int u = 0; u < 5; u++) {
            float4 gb = cbox[n + u]; float s6 = cssa[n + u];
            float w0 = fminf(x20, gb.z) - fmaxf(x10, gb.x);
            float h0 = fminf(y20, gb.w) - fmaxf(y10, gb.y);
            m0 = fmaxf(m0, fmaf(fmaxf(w0, 0.0f), h0, -s6));
            float w1 = fminf(x21, gb.z) - fmaxf(x11, gb.x);
            float h1 = fminf(y21, gb.w) - fmaxf(y11, gb.y);
            m1 = fmaxf(m1, fmaf(fmaxf(w1, 0.0f), h1, -s6));
        }
    }
    float no = 0.0f;
    if (!(m0 > t0_)) no += noc0;
    if (!(m1 > t1_)) no += noc1;

    #pragma unroll
    for (int off = 16; off; off >>= 1) {
        no += __shfl_down_sync(0xffffffffu, no, off);
        pr += __shfl_down_sync(0xffffffffu, pr, off);
    }
    if (lane == 0) { sred[wid] = no; sred[8 + wid] = pr; }
    __syncthreads();
    if (tid == 0) {
        float s = 0.0f;
        #pragma unroll
        for (int i = 0; i < 8; i++) s += sred[i];
        g_noobj[blockIdx.x] = s;
    }
    if (tid == 32) {
        float s = 0.0f;
        #pragma unroll
        for (int i = 0; i < 8; i++) s += sred[8 + i];
        g_prior[blockIdx.x] = s;
    }
    if (tid == 64) {
        g_coord[blockIdx.x] = gc[0] + gc[1] + gc[2] + gc[3] + gc[4];
        g_obj[blockIdx.x]   = go[0] + go[1] + go[2] + go[3] + go[4];
        g_cls[blockIdx.x]   = gl[0] + gl[1] + gl[2] + gl[3] + gl[4];
    }

    // ---------------- last-block deterministic final combine ----------------
    __shared__ bool is_last;
    __shared__ float sm[40];
    __syncthreads();
    if (threadIdx.x == 0) {
        __threadfence();
        unsigned int c = atomicAdd(&g_count, 1u);
        is_last = (c == NBLOCKS - 1);
    }
    __syncthreads();
    if (!is_last) return;
    __threadfence();  // make all blocks' partials visible

    float a0 = 0.f, a1 = 0.f, a2 = 0.f, a3 = 0.f, a4 = 0.f;
    for (int i = tid; i < NBLOCKS; i += 256) {
        a0 += g_noobj[i]; a1 += g_prior[i];
        a2 += g_coord[i]; a3 += g_obj[i]; a4 += g_cls[i];
    }
    #pragma unroll
    for (int off = 16; off; off >>= 1) {
        a0 += __shfl_down_sync(0xffffffffu, a0, off);
        a1 += __shfl_down_sync(0xffffffffu, a1, off);
        a2 += __shfl_down_sync(0xffffffffu, a2, off);
        a3 += __shfl_down_sync(0xffffffffu, a3, off);
        a4 += __shfl_down_sync(0xffffffffu, a4, off);
    }
    if (lane == 0) {
        sm[wid] = a0; sm[8 + wid] = a1; sm[16 + wid] = a2; sm[24 + wid] = a3; sm[32 + wid] = a4;
    }
    __syncthreads();
    if (tid == 0) {
        float t0 = 0.f, t1 = 0.f, t2 = 0.f, t3 = 0.f, t4 = 0.f;
        #pragma unroll
        for (int i = 0; i < 8; i++) {
            t0 += sm[i]; t1 += sm[8 + i]; t2 += sm[16 + i]; t3 += sm[24 + i]; t4 += sm[32 + i];
        }
        float lp = (seen[0] < 12800) ? 0.01f : 0.0f;
        out[0] = t4 + t0 + 5.0f * t3 + t2 + lp * t1;
        g_count = 0;   // reset for next graph replay
    }
}

extern "C" void kernel_launch(void* const* d_in, const int* in_sizes, int n_in,
                              void* d_out, int out_size) {
    const float* pred = (const float*)d_in[0];
    const float* gt   = (const float*)d_in[1];
    const float* anc  = (const float*)d_in[2];
    const int*   seen = (const int*)d_in[3];
    (void)in_sizes; (void)n_in; (void)out_size;

    fused_kernel<<<NBLOCKS, 256>>>(pred, gt, anc, seen, (float*)d_out);
}